// round 7
// baseline (speedup 1.0000x reference)
#include <cuda_runtime.h>
#include <cuda_bf16.h>
#include <cuda_fp8.h>
#include <cstdint>

#define SEQ   2048
#define BH    64
#define PADH  72     // bf16 smem row stride (elements)
#define PK8   80     // fp8 smem row stride (bytes): 20 words -> conflict-free
typedef __nv_bfloat16 bf16;

__device__ bf16    g_Wqh[4096], g_Wkh[4096], g_Wvh[4096], g_Eh[4096];
__device__ float   g_bq[64], g_bk[64], g_bv[64], g_be[64];
__device__ uint8_t g_Q8[BH*SEQ*64];
__device__ uint8_t g_K8[BH*SEQ*64];
__device__ uint8_t g_V8T[BH*64*SEQ];   // [bh][d][seq], x16 scale

// ---------------- helpers ----------------
__device__ __forceinline__ uint32_t packbf(float a, float b) {
    __nv_bfloat162 h = __floats2bfloat162_rn(a, b);
    return *reinterpret_cast<uint32_t*>(&h);
}
__device__ __forceinline__ float ex2(float x) {
    float y; asm("ex2.approx.ftz.f32 %0, %1;" : "=f"(y) : "f"(x)); return y;
}
__device__ __forceinline__ uint8_t fp8_1(float a) {
    return (uint8_t)__nv_cvt_float_to_fp8(a, __NV_SATFINITE, __NV_E4M3);
}
__device__ __forceinline__ uint16_t pack8(float a, float b) {
    uint16_t lo = (uint16_t)__nv_cvt_float_to_fp8(a, __NV_SATFINITE, __NV_E4M3);
    uint16_t hi = (uint16_t)__nv_cvt_float_to_fp8(b, __NV_SATFINITE, __NV_E4M3);
    return (uint16_t)(lo | (hi << 8));
}
__device__ __forceinline__ uint32_t prmt(uint32_t a, uint32_t b, uint32_t sel) {
    uint32_t d; asm("prmt.b32 %0, %1, %2, %3;" : "=r"(d) : "r"(a), "r"(b), "r"(sel)); return d;
}
__device__ __forceinline__ void mma16(float* d, const uint32_t* a, uint32_t b0, uint32_t b1) {
    asm volatile("mma.sync.aligned.m16n8k16.row.col.f32.bf16.bf16.f32 "
        "{%0,%1,%2,%3}, {%4,%5,%6,%7}, {%8,%9}, {%0,%1,%2,%3};"
        : "+f"(d[0]), "+f"(d[1]), "+f"(d[2]), "+f"(d[3])
        : "r"(a[0]), "r"(a[1]), "r"(a[2]), "r"(a[3]), "r"(b0), "r"(b1));
}
__device__ __forceinline__ void mma32f8(float* d, const uint32_t* a, uint32_t b0, uint32_t b1) {
    asm volatile("mma.sync.aligned.m16n8k32.row.col.f32.e4m3.e4m3.f32 "
        "{%0,%1,%2,%3}, {%4,%5,%6,%7}, {%8,%9}, {%0,%1,%2,%3};"
        : "+f"(d[0]), "+f"(d[1]), "+f"(d[2]), "+f"(d[3])
        : "r"(a[0]), "r"(a[1]), "r"(a[2]), "r"(a[3]), "r"(b0), "r"(b1));
}
__device__ __forceinline__ uint32_t sptr(const void* p) {
    return (uint32_t)__cvta_generic_to_shared(p);
}
__device__ __forceinline__ void cp16(uint32_t dst, const void* src) {
    asm volatile("cp.async.ca.shared.global [%0], [%1], 16;" :: "r"(dst), "l"(src));
}
__device__ __forceinline__ void cpcommit() { asm volatile("cp.async.commit_group;"); }
template<int N> __device__ __forceinline__ void cpwait() {
    asm volatile("cp.async.wait_group %0;" :: "n"(N));
}

// ---------------- kernel 1: precompute ----------------
__global__ void precompute_kernel(
    const float* __restrict__ Wi,  const float* __restrict__ bi,
    const float* __restrict__ Wq,  const float* __restrict__ bq,
    const float* __restrict__ Wk,  const float* __restrict__ bk,
    const float* __restrict__ Wv,  const float* __restrict__ bv,
    const float* __restrict__ Wc,  const float* __restrict__ bc,
    const float* __restrict__ Wci, const float* __restrict__ bci,
    const float* __restrict__ Wm,  const float* __restrict__ bm,
    const float* __restrict__ Wmi, const float* __restrict__ bmi)
{
    const int blk = blockIdx.x, tid = threadIdx.x;
    if (blk < 3) {
        __shared__ float A[4096], B[4096];
        const float* Wx = (blk == 0) ? Wq : (blk == 1) ? Wk : Wv;
        bf16* dst       = (blk == 0) ? g_Wqh : (blk == 1) ? g_Wkh : g_Wvh;
        for (int i = tid; i < 4096; i += 256) { A[i] = Wx[i]; B[i] = Wi[i]; }
        __syncthreads();
        for (int idx = tid; idx < 4096; idx += 256) {
            int o = idx >> 6, i = idx & 63;
            float a = 0.f;
            for (int j = 0; j < 64; j++) a += A[o*64 + j] * B[j*64 + i];
            dst[idx] = __float2bfloat16_rn(a);
        }
    } else if (blk == 3) {
        for (int tt = tid; tt < 192; tt += 256) {
            int mat = tt >> 6, o = tt & 63;
            const float* Wx = (mat == 0) ? Wq : (mat == 1) ? Wk : Wv;
            const float* bx = (mat == 0) ? bq : (mat == 1) ? bk : bv;
            float* dst      = (mat == 0) ? g_bq : (mat == 1) ? g_bk : g_bv;
            float a = bx[o];
            for (int j = 0; j < 64; j++) a += Wx[o*64 + j] * bi[j];
            dst[o] = a;
        }
    } else {
        __shared__ float M1[4096], M2[4096], b1s[64];
        for (int idx = tid; idx < 4096; idx += 256) {
            int o = idx >> 6, i = idx & 63;
            float a1 = 0.f;
            for (int j = 0; j < 8; j++) a1 += Wci[o*8 + j] * Wc[j*64 + i];
            M1[idx] = a1;
            float a2 = 0.f;
            for (int j = 0; j < 4; j++) a2 += Wmi[o*4 + j] * Wm[j*64 + i];
            M2[idx] = a2;
        }
        for (int o = tid; o < 64; o += 256) {
            float a = bci[o];
            for (int j = 0; j < 8; j++) a += Wci[o*8 + j] * bc[j];
            b1s[o] = a;
        }
        __syncthreads();
        for (int idx = tid; idx < 4096; idx += 256) {
            int o = idx >> 6, i = idx & 63;
            float e = 0.f;
            for (int j = 0; j < 64; j++) e += M2[o*64 + j] * M1[j*64 + i];
            g_Eh[idx] = __float2bfloat16_rn(e);
        }
        for (int o = tid; o < 64; o += 256) {
            float a = bmi[o];
            for (int j = 0; j < 4; j++)  a += Wmi[o*4 + j] * bm[j];
            for (int j = 0; j < 64; j++) a += M2[o*64 + j] * b1s[j];
            g_be[o] = a;
        }
    }
}

// ---------------- kernel 2: QKV projection (bf16 mma; Q,K,V -> fp8 x16) ----------------
__global__ __launch_bounds__(256) void qkv_kernel(const float* __restrict__ x)
{
    __shared__ __align__(16) bf16 xs[128*PADH];
    __shared__ __align__(16) bf16 ws[3][64*PADH];   // ws[0] reused as V-transpose buffer
    const int s0 = blockIdx.x * 128;
    const int bh = blockIdx.y;
    const int b  = bh >> 4, h = bh & 15;
    const int tid = threadIdx.x;
    const int w = tid >> 5, lane = tid & 31, g = lane >> 2, t = lane & 3;
    const int r0 = w*16 + g;

    const float* xbase = x + ((size_t)(b*SEQ + s0))*1024 + h*64;
    for (int p = tid; p < 4096; p += 256) {
        int r = p >> 5, c2 = (p & 31) * 2;
        float2 v = *(const float2*)&xbase[(size_t)r*1024 + c2];
        *(uint32_t*)&xs[r*PADH + c2] = packbf(v.x, v.y);
    }
    {
        const uint32_t* wsrc[3] = {(const uint32_t*)g_Wqh, (const uint32_t*)g_Wkh, (const uint32_t*)g_Wvh};
        for (int m = 0; m < 3; m++)
            for (int p = tid; p < 2048; p += 256) {
                int r = p >> 5, c2 = (p & 31) * 2;
                *(uint32_t*)&ws[m][r*PADH + c2] = wsrc[m][p];
            }
    }
    __syncthreads();

    uint32_t a[4][4];
#pragma unroll
    for (int kk = 0; kk < 4; kk++) {
        int c0 = 16*kk + 2*t;
        a[kk][0] = *(const uint32_t*)&xs[(r0    )*PADH + c0    ];
        a[kk][1] = *(const uint32_t*)&xs[(r0 + 8)*PADH + c0    ];
        a[kk][2] = *(const uint32_t*)&xs[(r0    )*PADH + c0 + 8];
        a[kk][3] = *(const uint32_t*)&xs[(r0 + 8)*PADH + c0 + 8];
    }
    const size_t base = (size_t)bh*SEQ + s0;

    // Q, K -> fp8 x16
    for (int mat = 0; mat < 2; mat++) {
        float acc[8][4];
#pragma unroll
        for (int j = 0; j < 8; j++)
#pragma unroll
            for (int q = 0; q < 4; q++) acc[j][q] = 0.f;
#pragma unroll
        for (int kk = 0; kk < 4; kk++)
#pragma unroll
            for (int j = 0; j < 8; j++) {
                uint32_t b0 = *(const uint32_t*)&ws[mat][(8*j + g)*PADH + 16*kk + 2*t    ];
                uint32_t b1 = *(const uint32_t*)&ws[mat][(8*j + g)*PADH + 16*kk + 2*t + 8];
                mma16(acc[j], a[kk], b0, b1);
            }
        const float* bp = (mat == 0) ? g_bq : g_bk;
        uint8_t* op = (mat == 0) ? g_Q8 : g_K8;
#pragma unroll
        for (int j = 0; j < 8; j++) {
            int col = 8*j + 2*t;
            float b0 = bp[col], b1 = bp[col+1];
            *(uint16_t*)&op[(base + r0    )*64 + col] = pack8((acc[j][0]+b0)*16.f, (acc[j][1]+b1)*16.f);
            *(uint16_t*)&op[(base + r0 + 8)*64 + col] = pack8((acc[j][2]+b0)*16.f, (acc[j][3]+b1)*16.f);
        }
    }

    // V: regs -> smem transpose -> g_V8T (fp8 x16)
    float vacc[8][4];
#pragma unroll
    for (int j = 0; j < 8; j++)
#pragma unroll
        for (int q = 0; q < 4; q++) vacc[j][q] = 0.f;
#pragma unroll
    for (int kk = 0; kk < 4; kk++)
#pragma unroll
        for (int j = 0; j < 8; j++) {
            uint32_t b0 = *(const uint32_t*)&ws[2][(8*j + g)*PADH + 16*kk + 2*t    ];
            uint32_t b1 = *(const uint32_t*)&ws[2][(8*j + g)*PADH + 16*kk + 2*t + 8];
            mma16(vacc[j], a[kk], b0, b1);
        }
    __syncthreads();
    uint8_t* vt = reinterpret_cast<uint8_t*>(&ws[0][0]);  // [64 d][144 seq bytes]
#pragma unroll
    for (int j = 0; j < 8; j++) {
        int col = 8*j + 2*t;
        float b0 = g_bv[col], b1 = g_bv[col+1];
        vt[(col    )*144 + r0    ] = fp8_1((vacc[j][0]+b0)*16.f);
        vt[(col + 1)*144 + r0    ] = fp8_1((vacc[j][1]+b1)*16.f);
        vt[(col    )*144 + r0 + 8] = fp8_1((vacc[j][2]+b0)*16.f);
        vt[(col + 1)*144 + r0 + 8] = fp8_1((vacc[j][3]+b1)*16.f);
    }
    __syncthreads();
    for (int p = tid; p < 512; p += 256) {
        int d = p >> 3, o16 = (p & 7) * 16;
        *(uint4*)&g_V8T[((size_t)bh*64 + d)*2048 + s0 + o16] = *(const uint4*)&vt[d*144 + o16];
    }
}

// ---------------- kernel 3: full-fp8 flash attention (register P transport) ----------------
// grid (16, 64), 256 threads (8 warps x 16 q-rows). Bc=64, 32 kv tiles, max-free softmax.
__global__ __launch_bounds__(256) void attn_kernel(float* __restrict__ out)
{
    __shared__ __align__(16) uint8_t K8s[3][64*PK8];   // 15360 B (reused for E)
    __shared__ __align__(16) uint8_t V8s[3][64*PK8];   // 15360 B ([d][seq])

    const int q0 = blockIdx.x * 128;
    const int bh = blockIdx.y;
    const int b  = bh >> 4, h = bh & 15;
    const int tid  = threadIdx.x;
    const int w    = tid >> 5, lane = tid & 31, g = lane >> 2, t = lane & 3;
    const int r0   = w*16 + g;

    // exp2 arg = s_acc * c;  c = (1/8)*log2(e)/256  (16x16 fp8 scale undo)
    const float cexp = 1.4426950408889634f / 2048.f;

    uint32_t aq[2][4];
    {
        const uint8_t* qp = g_Q8 + ((size_t)bh*SEQ + q0)*64;
#pragma unroll
        for (int kk = 0; kk < 2; kk++) {
            int c0 = 32*kk + 4*t;
            aq[kk][0] = *(const uint32_t*)&qp[(size_t)(r0    )*64 + c0     ];
            aq[kk][1] = *(const uint32_t*)&qp[(size_t)(r0 + 8)*64 + c0     ];
            aq[kk][2] = *(const uint32_t*)&qp[(size_t)(r0    )*64 + c0 + 16];
            aq[kk][3] = *(const uint32_t*)&qp[(size_t)(r0 + 8)*64 + c0 + 16];
        }
    }

    float oacc[8][4];
#pragma unroll
    for (int j = 0; j < 8; j++)
#pragma unroll
        for (int q = 0; q < 4; q++) oacc[j][q] = 0.f;
    float l_lo = 0.f, l_hi = 0.f;

    const uint8_t* Kg  = g_K8 + (size_t)bh*SEQ*64;
    const uint8_t* VTg = g_V8T + (size_t)bh*64*2048;
    const uint32_t ksb[3] = {sptr(K8s[0]), sptr(K8s[1]), sptr(K8s[2])};
    const uint32_t vsb[3] = {sptr(V8s[0]), sptr(V8s[1]), sptr(V8s[2])};

    auto issue_stage = [&](int st, int kt) {
        {   // K tile: [seq 64][d 64B], rows padded to 80
            int i = tid;
            uint32_t off = (uint32_t)(i >> 2)*PK8 + (uint32_t)(i & 3)*16;
            cp16(ksb[st] + off, Kg + (size_t)kt*4096 + i*16);
        }
        {   // V tile: [d 64][seq 64B], rows padded to 80
            int i = tid;
            int d = i >> 2, o16 = (i & 3) * 16;
            cp16(vsb[st] + (uint32_t)d*PK8 + (uint32_t)o16,
                 VTg + (size_t)d*2048 + kt*64 + o16);
        }
        cpcommit();
    };

    issue_stage(0, 0);
    issue_stage(1, 1);

    const int sl0 = 2*(t & 1), sl1 = sl0 + 1;   // quad source lanes for P shuffles
    const bool tlo = (t < 2);

    for (int kt = 0; kt < 32; kt++) {
        const int st = kt % 3;
        if (kt == 31) { cpwait<0>(); } else { cpwait<1>(); }
        __syncthreads();
        if (kt < 30) issue_stage((kt + 2) % 3, kt + 2);

        // ---- S = Q K^T (fp8) ----
        float s[8][4];
#pragma unroll
        for (int j = 0; j < 8; j++)
#pragma unroll
            for (int q = 0; q < 4; q++) s[j][q] = 0.f;
#pragma unroll
        for (int kk = 0; kk < 2; kk++)
#pragma unroll
            for (int j = 0; j < 8; j++) {
                const uint8_t* rowK = &K8s[st][(8*j + g)*PK8 + 32*kk];
                uint32_t b0 = *(const uint32_t*)&rowK[4*t];
                uint32_t b1 = *(const uint32_t*)&rowK[16 + 4*t];
                mma32f8(s[j], aq[kk], b0, b1);
            }

        // ---- max-free softmax; W[j] = {row g pair | row g+8 pair} fp8 ----
        uint32_t W[8];
#pragma unroll
        for (int j = 0; j < 8; j++) {
            float e0 = ex2(s[j][0]*cexp), e1 = ex2(s[j][1]*cexp);
            float e2 = ex2(s[j][2]*cexp), e3 = ex2(s[j][3]*cexp);
            l_lo += e0 + e1;
            l_hi += e2 + e3;
            W[j] = (uint32_t)pack8(e0, e1) | ((uint32_t)pack8(e2, e3) << 16);
        }

        // ---- build fp8 A-fragments of P via quad shuffles (no smem) ----
        uint32_t pa[2][4];
#pragma unroll
        for (int kk = 0; kk < 2; kk++) {
            uint32_t A0 = __shfl_sync(0xffffffffu, W[4*kk    ], sl0, 4);
            uint32_t A1 = __shfl_sync(0xffffffffu, W[4*kk    ], sl1, 4);
            uint32_t B0 = __shfl_sync(0xffffffffu, W[4*kk + 1], sl0, 4);
            uint32_t B1 = __shfl_sync(0xffffffffu, W[4*kk + 1], sl1, 4);
            uint32_t X0 = tlo ? A0 : B0, X1 = tlo ? A1 : B1;
            pa[kk][0] = prmt(X0, X1, 0x5410u);   // row g,   k 32kk+4t..+3
            pa[kk][1] = prmt(X0, X1, 0x7632u);   // row g+8, same
            uint32_t C0 = __shfl_sync(0xffffffffu, W[4*kk + 2], sl0, 4);
            uint32_t C1 = __shfl_sync(0xffffffffu, W[4*kk + 2], sl1, 4);
            uint32_t D0 = __shfl_sync(0xffffffffu, W[4*kk + 3], sl0, 4);
            uint32_t D1 = __shfl_sync(0xffffffffu, W[4*kk + 3], sl1, 4);
            uint32_t Y0 = tlo ? C0 : D0, Y1 = tlo ? C1 : D1;
            pa[kk][2] = prmt(Y0, Y1, 0x5410u);   // row g,   k 32kk+16+4t..+3
            pa[kk][3] = prmt(Y0, Y1, 0x7632u);   // row g+8, same
        }

        // ---- O += P V (fp8; B from transposed V tile) ----
#pragma unroll
        for (int kk = 0; kk < 2; kk++)
#pragma unroll
            for (int J = 0; J < 8; J++) {
                const uint8_t* rowV = &V8s[st][(8*J + g)*PK8 + 32*kk];
                uint32_t b0 = *(const uint32_t*)&rowV[4*t];
                uint32_t b1 = *(const uint32_t*)&rowV[16 + 4*t];
                mma32f8(oacc[J], pa[kk], b0, b1);
            }
    }

    // ---- l quad-reduction; normalize (undo V x16); pack O as bf16 A-frags ----
#pragma unroll
    for (int off = 1; off < 4; off <<= 1) {
        l_lo += __shfl_xor_sync(0xffffffffu, l_lo, off);
        l_hi += __shfl_xor_sync(0xffffffffu, l_hi, off);
    }
    float il_lo = 1.f / (16.f * l_lo), il_hi = 1.f / (16.f * l_hi);
    uint32_t ea[4][4];
#pragma unroll
    for (int kk = 0; kk < 4; kk++) {
        ea[kk][0] = packbf(oacc[2*kk    ][0]*il_lo, oacc[2*kk    ][1]*il_lo);
        ea[kk][1] = packbf(oacc[2*kk    ][2]*il_hi, oacc[2*kk    ][3]*il_hi);
        ea[kk][2] = packbf(oacc[2*kk + 1][0]*il_lo, oacc[2*kk + 1][1]*il_lo);
        ea[kk][3] = packbf(oacc[2*kk + 1][2]*il_hi, oacc[2*kk + 1][3]*il_hi);
    }

    // ---- load E (overlay on K8s) ----
    __syncthreads();
    bf16* Es = reinterpret_cast<bf16*>(&K8s[0][0]);
    for (int p = tid; p < 2048; p += 256) {
        int r = p >> 5, c2 = (p & 31) * 2;
        *(uint32_t*)&Es[r*PADH + c2] = ((const uint32_t*)g_Eh)[p];
    }
    __syncthreads();

    // ---- epilogue: out = O E^T + be (bf16 mma) ----
    float e[8][4];
#pragma unroll
    for (int j = 0; j < 8; j++)
#pragma unroll
        for (int q = 0; q < 4; q++) e[j][q] = 0.f;
#pragma unroll
    for (int kk = 0; kk < 4; kk++)
#pragma unroll
    for (int j = 0; j < 8; j++) {
            uint32_t b0 = *(const uint32_t*)&Es[(8*j + g)*PADH + 16*kk + 2*t    ];
            uint32_t b1 = *(const uint32_t*)&Es[(8*j + g)*PADH + 16*kk + 2*t + 8];
            mma16(e[j], ea[kk], b0, b1);
        }

    float* ob = out + ((size_t)(b*SEQ + q0))*1024 + h*64;
#pragma unroll
    for (int j = 0; j < 8; j++) {
        int col = 8*j + 2*t;
        float b0 = __ldg(&g_be[col]), b1 = __ldg(&g_be[col + 1]);
        *(float2*)&ob[(size_t)(r0    )*1024 + col] = make_float2(e[j][0] + b0, e[j][1] + b1);
        *(float2*)&ob[(size_t)(r0 + 8)*1024 + col] = make_float2(e[j][2] + b0, e[j][3] + b1);
    }
}

// ---------------- launch ----------------
extern "C" void kernel_launch(void* const* d_in, const int* in_sizes, int n_in,
                              void* d_out, int out_size)
{
    (void)in_sizes; (void)n_in; (void)out_size;
    const float* x   = (const float*)d_in[0];
    const float* Wi  = (const float*)d_in[1];
    const float* bi  = (const float*)d_in[2];
    const float* Wq  = (const float*)d_in[3];
    const float* bq  = (const float*)d_in[4];
    const float* Wk  = (const float*)d_in[5];
    const float* bk  = (const float*)d_in[6];
    const float* Wv  = (const float*)d_in[7];
    const float* bv  = (const float*)d_in[8];
    const float* Wc  = (const float*)d_in[9];
    const float* bc  = (const float*)d_in[10];
    const float* Wci = (const float*)d_in[11];
    const float* bci = (const float*)d_in[12];
    const float* Wm  = (const float*)d_in[13];
    const float* bm  = (const float*)d_in[14];
    const float* Wmi = (const float*)d_in[15];
    const float* bmi = (const float*)d_in[16];

    precompute_kernel<<<5, 256>>>(Wi, bi, Wq, bq, Wk, bk, Wv, bv,
                                  Wc, bc, Wci, bci, Wm, bm, Wmi, bmi);
    qkv_kernel<<<dim3(16, 64), 256>>>(x);
    attn_kernel<<<dim3(16, 64), 256>>>((float*)d_out);
}

// round 8
// speedup vs baseline: 1.1773x; 1.1773x over previous
#include <cuda_runtime.h>
#include <cuda_bf16.h>
#include <cuda_fp8.h>
#include <cstdint>

#define SEQ   2048
#define BH    64
#define PADH  72     // bf16 V/E smem row stride
#define PK8   80     // fp8 K smem row stride (bytes): 20 words -> conflict-free
typedef __nv_bfloat16 bf16;

__device__ bf16    g_Wqh[4096], g_Wkh[4096], g_Wvh[4096], g_Eh[4096];
__device__ float   g_bq[64], g_bk[64], g_bv[64], g_be[64];
__device__ uint8_t g_Q8[BH*SEQ*64];
__device__ uint8_t g_K8[BH*SEQ*64];
__device__ bf16    g_Vh[BH*SEQ*64];

// ---------------- helpers ----------------
__device__ __forceinline__ uint32_t packbf(float a, float b) {
    __nv_bfloat162 h = __floats2bfloat162_rn(a, b);
    return *reinterpret_cast<uint32_t*>(&h);
}
__device__ __forceinline__ float ex2(float x) {
    float y; asm("ex2.approx.ftz.f32 %0, %1;" : "=f"(y) : "f"(x)); return y;
}
__device__ __forceinline__ uint16_t pack8(float a, float b) {
    uint16_t lo = (uint16_t)__nv_cvt_float_to_fp8(a, __NV_SATFINITE, __NV_E4M3);
    uint16_t hi = (uint16_t)__nv_cvt_float_to_fp8(b, __NV_SATFINITE, __NV_E4M3);
    return (uint16_t)(lo | (hi << 8));
}
__device__ __forceinline__ void mma16(float* d, const uint32_t* a, uint32_t b0, uint32_t b1) {
    asm volatile("mma.sync.aligned.m16n8k16.row.col.f32.bf16.bf16.f32 "
        "{%0,%1,%2,%3}, {%4,%5,%6,%7}, {%8,%9}, {%0,%1,%2,%3};"
        : "+f"(d[0]), "+f"(d[1]), "+f"(d[2]), "+f"(d[3])
        : "r"(a[0]), "r"(a[1]), "r"(a[2]), "r"(a[3]), "r"(b0), "r"(b1));
}
__device__ __forceinline__ void mma32f8(float* d, const uint32_t* a, uint32_t b0, uint32_t b1) {
    asm volatile("mma.sync.aligned.m16n8k32.row.col.f32.e4m3.e4m3.f32 "
        "{%0,%1,%2,%3}, {%4,%5,%6,%7}, {%8,%9}, {%0,%1,%2,%3};"
        : "+f"(d[0]), "+f"(d[1]), "+f"(d[2]), "+f"(d[3])
        : "r"(a[0]), "r"(a[1]), "r"(a[2]), "r"(a[3]), "r"(b0), "r"(b1));
}
__device__ __forceinline__ void ldm4(uint32_t* r, uint32_t addr) {
    asm volatile("ldmatrix.sync.aligned.m8n8.x4.shared.b16 {%0,%1,%2,%3}, [%4];"
        : "=r"(r[0]), "=r"(r[1]), "=r"(r[2]), "=r"(r[3]) : "r"(addr));
}
__device__ __forceinline__ void ldm4t(uint32_t* r, uint32_t addr) {
    asm volatile("ldmatrix.sync.aligned.m8n8.x4.trans.shared.b16 {%0,%1,%2,%3}, [%4];"
        : "=r"(r[0]), "=r"(r[1]), "=r"(r[2]), "=r"(r[3]) : "r"(addr));
}
__device__ __forceinline__ uint32_t sptr(const void* p) {
    return (uint32_t)__cvta_generic_to_shared(p);
}
__device__ __forceinline__ void cp16(uint32_t dst, const void* src) {
    asm volatile("cp.async.ca.shared.global [%0], [%1], 16;" :: "r"(dst), "l"(src));
}
__device__ __forceinline__ void cpcommit() { asm volatile("cp.async.commit_group;"); }
template<int N> __device__ __forceinline__ void cpwait() {
    asm volatile("cp.async.wait_group %0;" :: "n"(N));
}

// ---------------- kernel 1: precompute ----------------
__global__ void precompute_kernel(
    const float* __restrict__ Wi,  const float* __restrict__ bi,
    const float* __restrict__ Wq,  const float* __restrict__ bq,
    const float* __restrict__ Wk,  const float* __restrict__ bk,
    const float* __restrict__ Wv,  const float* __restrict__ bv,
    const float* __restrict__ Wc,  const float* __restrict__ bc,
    const float* __restrict__ Wci, const float* __restrict__ bci,
    const float* __restrict__ Wm,  const float* __restrict__ bm,
    const float* __restrict__ Wmi, const float* __restrict__ bmi)
{
    const int blk = blockIdx.x, tid = threadIdx.x;
    if (blk < 3) {
        __shared__ float A[4096], B[4096];
        const float* Wx = (blk == 0) ? Wq : (blk == 1) ? Wk : Wv;
        bf16* dst       = (blk == 0) ? g_Wqh : (blk == 1) ? g_Wkh : g_Wvh;
        for (int i = tid; i < 4096; i += 256) { A[i] = Wx[i]; B[i] = Wi[i]; }
        __syncthreads();
        for (int idx = tid; idx < 4096; idx += 256) {
            int o = idx >> 6, i = idx & 63;
            float a = 0.f;
            for (int j = 0; j < 64; j++) a += A[o*64 + j] * B[j*64 + i];
            dst[idx] = __float2bfloat16_rn(a);
        }
    } else if (blk == 3) {
        for (int tt = tid; tt < 192; tt += 256) {
            int mat = tt >> 6, o = tt & 63;
            const float* Wx = (mat == 0) ? Wq : (mat == 1) ? Wk : Wv;
            const float* bx = (mat == 0) ? bq : (mat == 1) ? bk : bv;
            float* dst      = (mat == 0) ? g_bq : (mat == 1) ? g_bk : g_bv;
            float a = bx[o];
            for (int j = 0; j < 64; j++) a += Wx[o*64 + j] * bi[j];
            dst[o] = a;
        }
    } else {
        __shared__ float M1[4096], M2[4096], b1s[64];
        for (int idx = tid; idx < 4096; idx += 256) {
            int o = idx >> 6, i = idx & 63;
            float a1 = 0.f;
            for (int j = 0; j < 8; j++) a1 += Wci[o*8 + j] * Wc[j*64 + i];
            M1[idx] = a1;
            float a2 = 0.f;
            for (int j = 0; j < 4; j++) a2 += Wmi[o*4 + j] * Wm[j*64 + i];
            M2[idx] = a2;
        }
        for (int o = tid; o < 64; o += 256) {
            float a = bci[o];
            for (int j = 0; j < 8; j++) a += Wci[o*8 + j] * bc[j];
            b1s[o] = a;
        }
        __syncthreads();
        for (int idx = tid; idx < 4096; idx += 256) {
            int o = idx >> 6, i = idx & 63;
            float e = 0.f;
            for (int j = 0; j < 64; j++) e += M2[o*64 + j] * M1[j*64 + i];
            g_Eh[idx] = __float2bfloat16_rn(e);
        }
        for (int o = tid; o < 64; o += 256) {
            float a = bmi[o];
            for (int j = 0; j < 4; j++)  a += Wmi[o*4 + j] * bm[j];
            for (int j = 0; j < 64; j++) a += M2[o*64 + j] * b1s[j];
            g_be[o] = a;
        }
    }
}

// ---------------- kernel 2: QKV projection (bf16 mma; Q,K -> fp8 x16, V -> bf16) ----------------
__global__ __launch_bounds__(256) void qkv_kernel(const float* __restrict__ x)
{
    __shared__ __align__(16) bf16 xs[128*PADH];
    __shared__ __align__(16) bf16 ws[3][64*PADH];
    const int s0 = blockIdx.x * 128;
    const int bh = blockIdx.y;
    const int b  = bh >> 4, h = bh & 15;
    const int tid = threadIdx.x;
    const int w = tid >> 5, lane = tid & 31, g = lane >> 2, t = lane & 3;
    const int r0 = w*16 + g;

    const float* xbase = x + ((size_t)(b*SEQ + s0))*1024 + h*64;
    for (int p = tid; p < 4096; p += 256) {
        int r = p >> 5, c2 = (p & 31) * 2;
        float2 v = *(const float2*)&xbase[(size_t)r*1024 + c2];
        *(uint32_t*)&xs[r*PADH + c2] = packbf(v.x, v.y);
    }
    {
        const uint32_t* wsrc[3] = {(const uint32_t*)g_Wqh, (const uint32_t*)g_Wkh, (const uint32_t*)g_Wvh};
        for (int m = 0; m < 3; m++)
            for (int p = tid; p < 2048; p += 256) {
                int r = p >> 5, c2 = (p & 31) * 2;
                *(uint32_t*)&ws[m][r*PADH + c2] = wsrc[m][p];
            }
    }
    __syncthreads();

    uint32_t a[4][4];
#pragma unroll
    for (int kk = 0; kk < 4; kk++) {
        int c0 = 16*kk + 2*t;
        a[kk][0] = *(const uint32_t*)&xs[(r0    )*PADH + c0    ];
        a[kk][1] = *(const uint32_t*)&xs[(r0 + 8)*PADH + c0    ];
        a[kk][2] = *(const uint32_t*)&xs[(r0    )*PADH + c0 + 8];
        a[kk][3] = *(const uint32_t*)&xs[(r0 + 8)*PADH + c0 + 8];
    }
    const size_t base = (size_t)bh*SEQ + s0;

    for (int mat = 0; mat < 3; mat++) {
        float acc[8][4];
#pragma unroll
        for (int j = 0; j < 8; j++)
#pragma unroll
            for (int q = 0; q < 4; q++) acc[j][q] = 0.f;
#pragma unroll
        for (int kk = 0; kk < 4; kk++)
#pragma unroll
            for (int j = 0; j < 8; j++) {
                uint32_t b0 = *(const uint32_t*)&ws[mat][(8*j + g)*PADH + 16*kk + 2*t    ];
                uint32_t b1 = *(const uint32_t*)&ws[mat][(8*j + g)*PADH + 16*kk + 2*t + 8];
                mma16(acc[j], a[kk], b0, b1);
            }
        if (mat < 2) {
            const float* bp = (mat == 0) ? g_bq : g_bk;
            uint8_t* op = (mat == 0) ? g_Q8 : g_K8;
#pragma unroll
            for (int j = 0; j < 8; j++) {
                int col = 8*j + 2*t;
                float b0 = bp[col], b1 = bp[col+1];
                *(uint16_t*)&op[(base + r0    )*64 + col] = pack8((acc[j][0]+b0)*16.f, (acc[j][1]+b1)*16.f);
                *(uint16_t*)&op[(base + r0 + 8)*64 + col] = pack8((acc[j][2]+b0)*16.f, (acc[j][3]+b1)*16.f);
            }
        } else {
            bf16* op = g_Vh;
#pragma unroll
            for (int j = 0; j < 8; j++) {
                int col = 8*j + 2*t;
                float b0 = g_bv[col], b1 = g_bv[col+1];
                *(uint32_t*)&op[(base + r0    )*64 + col] = packbf(acc[j][0]+b0, acc[j][1]+b1);
                *(uint32_t*)&op[(base + r0 + 8)*64 + col] = packbf(acc[j][2]+b0, acc[j][3]+b1);
            }
        }
    }
}

// ---------------- kernel 3: flash attention (fp8 QK^T via ldmatrix, bf16 PV) ----------------
// grid (16, 64), 256 threads (8 warps x 16 q-rows). Bc=64, 32 kv tiles, max-free softmax.
// 3-stage cp.async pipeline, one __syncthreads per tile.
__global__ __launch_bounds__(256) void attn_kernel(float* __restrict__ out)
{
    __shared__ __align__(16) uint8_t K8s[3][64*PK8];   // 15360 B (reused for E)
    __shared__ __align__(16) bf16    Vs[3][64*PADH];   // 27648 B

    const int q0 = blockIdx.x * 128;
    const int bh = blockIdx.y;
    const int b  = bh >> 4, h = bh & 15;
    const int tid  = threadIdx.x;
    const int w    = tid >> 5, lane = tid & 31, g = lane >> 2, t = lane & 3;
    const int r0   = w*16 + g;
    const int l7  = lane & 7;
    const int lq  = lane >> 3;         // K-ldmatrix tile select (byte offset /16)
    const int lt1 = (lane >> 3) & 1;
    const int lt2 = lane >> 4;

    // exp2 arg = s_acc * c;  c = (1/8)*log2(e)/256  (16x16 fp8 scale undo)
    const float cexp = 1.4426950408889634f / 2048.f;

    uint32_t aq[2][4];
    {
        const uint8_t* qp = g_Q8 + ((size_t)bh*SEQ + q0)*64;
#pragma unroll
        for (int kk = 0; kk < 2; kk++) {
            int c0 = 32*kk + 4*t;
            aq[kk][0] = *(const uint32_t*)&qp[(size_t)(r0    )*64 + c0     ];
            aq[kk][1] = *(const uint32_t*)&qp[(size_t)(r0 + 8)*64 + c0     ];
            aq[kk][2] = *(const uint32_t*)&qp[(size_t)(r0    )*64 + c0 + 16];
            aq[kk][3] = *(const uint32_t*)&qp[(size_t)(r0 + 8)*64 + c0 + 16];
        }
    }

    float oacc[8][4];
#pragma unroll
    for (int j = 0; j < 8; j++)
#pragma unroll
        for (int q = 0; q < 4; q++) oacc[j][q] = 0.f;
    float l_lo = 0.f, l_hi = 0.f;

    const uint8_t* Kg = g_K8 + (size_t)bh*SEQ*64;
    const bf16*    Vg = g_Vh + (size_t)bh*SEQ*64;
    const uint32_t ksb[3] = {sptr(K8s[0]), sptr(K8s[1]), sptr(K8s[2])};
    const uint32_t vsb[3] = {sptr(Vs[0]),  sptr(Vs[1]),  sptr(Vs[2])};

    auto issue_stage = [&](int st, int kt) {
        {   // K: 256 x 16B chunks, rows padded to 80B
            int i = tid;
            uint32_t off = (uint32_t)(i >> 2)*PK8 + (uint32_t)(i & 3)*16;
            cp16(ksb[st] + off, Kg + (size_t)kt*4096 + i*16);
        }
#pragma unroll
        for (int c = 0; c < 2; c++) {   // V: 512 x 16B chunks
            int i = c*256 + tid;
            uint32_t off = (uint32_t)((i >> 3)*PADH + (i & 7)*8) * 2;
            cp16(vsb[st] + off, Vg + (size_t)kt*4096 + i*8);
        }
        cpcommit();
    };

    issue_stage(0, 0);
    issue_stage(1, 1);

    // K ldmatrix lane address component (within a j-group): row l7, byte-half lq*16
    const uint32_t koff = (uint32_t)(l7*PK8 + lq*16);

    for (int kt = 0; kt < 32; kt++) {
        const int st = kt % 3;
        if (kt == 31) { cpwait<0>(); } else { cpwait<1>(); }
        __syncthreads();
        if (kt < 30) issue_stage((kt + 2) % 3, kt + 2);

        // ---- S = Q K^T (fp8; one ldmatrix.x4 per j-group serves both kk) ----
        float s[8][4];
#pragma unroll
        for (int j = 0; j < 8; j++)
#pragma unroll
            for (int q = 0; q < 4; q++) s[j][q] = 0.f;
#pragma unroll
        for (int j = 0; j < 8; j++) {
            uint32_t bk[4];
            ldm4(bk, ksb[st] + (uint32_t)(8*j)*PK8 + koff);
            mma32f8(s[j], aq[0], bk[0], bk[1]);
            mma32f8(s[j], aq[1], bk[2], bk[3]);
        }

        // ---- max-free softmax: p = exp2(s*c); pack P as bf16 A-frags (C==A layout) ----
        uint32_t pa[4][4];
#pragma unroll
        for (int j = 0; j < 4; j++) {
            float e0 = ex2(s[2*j  ][0]*cexp), e1 = ex2(s[2*j  ][1]*cexp);
            float e2 = ex2(s[2*j  ][2]*cexp), e3 = ex2(s[2*j  ][3]*cexp);
            float f0 = ex2(s[2*j+1][0]*cexp), f1 = ex2(s[2*j+1][1]*cexp);
            float f2 = ex2(s[2*j+1][2]*cexp), f3 = ex2(s[2*j+1][3]*cexp);
            l_lo += (e0 + e1) + (f0 + f1);
            l_hi += (e2 + e3) + (f2 + f3);
            pa[j][0] = packbf(e0, e1);
            pa[j][1] = packbf(e2, e3);
            pa[j][2] = packbf(f0, f1);
            pa[j][3] = packbf(f2, f3);
        }

        // ---- O += P V (bf16, trans-ldmatrix B from row-major V) ----
#pragma unroll
        for (int J = 0; J < 4; J++) {
            uint32_t colV = (uint32_t)(8*(2*J + lt2) * 2);
#pragma unroll
            for (int kk = 0; kk < 4; kk++) {
                uint32_t bv[4];
                ldm4t(bv, vsb[st] + (uint32_t)((16*kk + 8*lt1 + l7) * (PADH*2)) + colV);
                mma16(oacc[2*J    ], pa[kk], bv[0], bv[1]);
                mma16(oacc[2*J + 1], pa[kk], bv[2], bv[3]);
            }
        }
    }

    // ---- l quad-reduction; normalize; pack O as bf16 A-frags ----
#pragma unroll
    for (int off = 1; off < 4; off <<= 1) {
        l_lo += __shfl_xor_sync(0xffffffffu, l_lo, off);
        l_hi += __shfl_xor_sync(0xffffffffu, l_hi, off);
    }
    float il_lo = 1.f / l_lo, il_hi = 1.f / l_hi;
    uint32_t ea[4][4];
#pragma unroll
    for (int kk = 0; kk < 4; kk++) {
        ea[kk][0] = packbf(oacc[2*kk    ][0]*il_lo, oacc[2*kk    ][1]*il_lo);
        ea[kk][1] = packbf(oacc[2*kk    ][2]*il_hi, oacc[2*kk    ][3]*il_hi);
        ea[kk][2] = packbf(oacc[2*kk + 1][0]*il_lo, oacc[2*kk + 1][1]*il_lo);
        ea[kk][3] = packbf(oacc[2*kk + 1][2]*il_hi, oacc[2*kk + 1][3]*il_hi);
    }

    // ---- load E (overlay on K8s) ----
    __syncthreads();
    bf16* Es = reinterpret_cast<bf16*>(&K8s[0][0]);
    for (int p = tid; p < 2048; p += 256) {
        int r = p >> 5, c2 = (p & 31) * 2;
        *(uint32_t*)&Es[r*PADH + c2] = ((const uint32_t*)g_Eh)[p];
    }
    __syncthreads();

    // ---- epilogue: out = O E^T + be (bf16 mma) ----
    float e[8][4];
#pragma unroll
    for (int j = 0; j < 8; j++)
#pragma unroll
        for (int q = 0; q < 4; q++) e[j][q] = 0.f;
#pragma unroll
    for (int kk = 0; kk < 4; kk++)
#pragma unroll
        for (int j = 0; j < 8; j++) {
            uint32_t b0 = *(const uint32_t*)&Es[(8*j + g)*PADH + 16*kk + 2*t    ];
            uint32_t b1 = *(const uint32_t*)&Es[(8*j + g)*PADH + 16*kk + 2*t + 8];
            mma16(e[j], ea[kk], b0, b1);
        }

    float* ob = out + ((size_t)(b*SEQ + q0))*1024 + h*64;
#pragma unroll
    for (int j = 0; j < 8; j++) {
        int col = 8*j + 2*t;
        float b0 = __ldg(&g_be[col]), b1 = __ldg(&g_be[col + 1]);
        *(float2*)&ob[(size_t)(r0    )*1024 + col] = make_float2(e[j][0] + b0, e[j][1] + b1);
        *(float2*)&ob[(size_t)(r0 + 8)*1024 + col] = make_float2(e[j][2] + b0, e[j][3] + b1);
    }
}

// ---------------- launch ----------------
extern "C" void kernel_launch(void* const* d_in, const int* in_sizes, int n_in,
                              void* d_out, int out_size)
{
    (void)in_sizes; (void)n_in; (void)out_size;
    const float* x   = (const float*)d_in[0];
    const float* Wi  = (const float*)d_in[1];
    const float* bi  = (const float*)d_in[2];
    const float* Wq  = (const float*)d_in[3];
    const float* bq  = (const float*)d_in[4];
    const float* Wk  = (const float*)d_in[5];
    const float* bk  = (const float*)d_in[6];
    const float* Wv  = (const float*)d_in[7];
    const float* bv  = (const float*)d_in[8];
    const float* Wc  = (const float*)d_in[9];
    const float* bc  = (const float*)d_in[10];
    const float* Wci = (const float*)d_in[11];
    const float* bci = (const float*)d_in[12];
    const float* Wm  = (const float*)d_in[13];
    const float* bm  = (const float*)d_in[14];
    const float* Wmi = (const float*)d_in[15];
    const float* bmi = (const float*)d_in[16];

    precompute_kernel<<<5, 256>>>(Wi, bi, Wq, bq, Wk, bk, Wv, bv,
                                  Wc, bc, Wci, bci, Wm, bm, Wmi, bmi);
    qkv_kernel<<<dim3(16, 64), 256>>>(x);
    attn_kernel<<<dim3(16, 64), 256>>>((float*)d_out);
}